// round 15
// baseline (speedup 1.0000x reference)
#include <cuda_runtime.h>
#include <cuda_fp16.h>
#include <cstdint>

#define DIMC 1024
#define DIMW 512                 /* packed half2 words per row */
#define NHEAD 16
#define HDIM 64
#define HDW 32
#define BATCH 4
#define SEQ 2048
#define MTOT (BATCH*SEQ)
#define NQKV (3*DIMC)

__device__ unsigned g_xtf [(size_t)MTOT*DIMW];
__device__ unsigned g_wqkv[(size_t)DIMW*NQKV];   // [kpair][n]
__device__ unsigned g_wprj[(size_t)DIMW*DIMC];   // [kpair][n]
__device__ unsigned g_qkv [(size_t)3*BATCH*NHEAD*SEQ*HDW];  // [3][B][H][S][dpair]
__device__ unsigned g_attn[(size_t)MTOT*DIMW];

__device__ __forceinline__ unsigned packh2(float a, float b){
    __half2 h = __floats2half2_rn(a,b);
    return *(unsigned*)&h;
}
__device__ __forceinline__ float2 uph2(unsigned u){
    __half2 h = *(__half2*)&u;
    return __half22float2(h);
}
__device__ __forceinline__ void mma16(float* c, const unsigned* a, const unsigned* b){
    asm volatile(
      "mma.sync.aligned.m16n8k16.row.col.f32.f16.f16.f32 "
      "{%0,%1,%2,%3},{%4,%5,%6,%7},{%8,%9},{%0,%1,%2,%3};\n"
      : "+f"(c[0]),"+f"(c[1]),"+f"(c[2]),"+f"(c[3])
      : "r"(a[0]),"r"(a[1]),"r"(a[2]),"r"(a[3]),"r"(b[0]),"r"(b[1]));
}
__device__ __forceinline__ uint32_t smem_u32(const void* p){
    uint32_t a;
    asm("{ .reg .u64 t; cvta.to.shared.u64 t, %1; cvt.u32.u64 %0, t; }":"=r"(a):"l"(p));
    return a;
}
__device__ __forceinline__ void cpa16(uint32_t dst, const void* src){
    asm volatile("cp.async.cg.shared.global [%0], [%1], 16;" :: "r"(dst), "l"(src));
}
#define CPA_COMMIT() asm volatile("cp.async.commit_group;" ::: "memory")
__device__ __forceinline__ void ldmx4t(unsigned* r, uint32_t addr){
    asm volatile("ldmatrix.sync.aligned.m8n8.x4.trans.shared.b16 {%0,%1,%2,%3}, [%4];"
        : "=r"(r[0]),"=r"(r[1]),"=r"(r[2]),"=r"(r[3]) : "r"(addr));
}

// ---------------------------------------------------------------------------
// Conversions
// ---------------------------------------------------------------------------
__global__ __launch_bounds__(256)
void cvt_x(const float4* __restrict__ src, uint2* __restrict__ dst, int n4)
{
    int i = blockIdx.x*256 + threadIdx.x;
    if(i < n4){
        float4 v = src[i];
        dst[i] = make_uint2(packh2(v.x,v.y), packh2(v.z,v.w));
    }
}
__global__ __launch_bounds__(256)
void cvt_w(const float* __restrict__ src, unsigned* __restrict__ dst, int N, int tot)
{
    int i = blockIdx.x*256 + threadIdx.x;
    if(i < tot){
        int kp = i / N, n = i - kp*N;
        dst[i] = packh2(src[(size_t)(2*kp)*N+n], src[(size_t)(2*kp+1)*N+n]);
    }
}

// ---------------------------------------------------------------------------
// fp16 GEMM, cp.async 3-stage ring: 64x64 warp tiles, 128 threads.
// A smem [m][kpair] stride 20 (conflict-free frag loads, contiguous rows for
// cp.async); B smem [kpair][n] stride 136.
// ---------------------------------------------------------------------------
#define AST 20
#define ABUFW (128*AST)          /* 2560 words */
#define BST 136
#define BBUFW (16*BST)           /* 2176 words */
#define STAGEW (ABUFW+BBUFW)     /* 4736 words */
#define GEMM_SMEM (3*STAGEW*4)   /* 56832 B */

template<int N, bool SCATTER>
__global__ __launch_bounds__(128)
void gemm_mma(const unsigned* __restrict__ A, const unsigned* __restrict__ B,
              const float* __restrict__ bias, float* __restrict__ out)
{
    extern __shared__ __align__(16) unsigned gsm[];
    const int tid=threadIdx.x, lane=tid&31, warp=tid>>5;
    const int g=lane>>2, tg=lane&3;
    const int mbase=(warp&1)*64, nbase=(warp>>1)*64;
    const int bm=blockIdx.y*128, bn=blockIdx.x*128;
    const unsigned* Ab = (SCATTER ? A : (const unsigned*)g_attn) + (size_t)bm*DIMW;
    const unsigned* Bb = B + bn;
    const uint32_t smb = smem_u32(gsm);

    // per-thread fill coordinates
    const int ar_ = tid>>2,  ac_ = (tid&3)<<2;     // A: row 0..31 (+32*i), col4
    const int br_ = tid>>5,  bc_ = (tid&31)<<2;    // B: row 0..3 (+4*i), col4

    float acc[4][8][4];
    #pragma unroll
    for(int i=0;i<4;i++)
      #pragma unroll
      for(int j=0;j<8;j++)
        #pragma unroll
        for(int k=0;k<4;k++) acc[i][j][k]=0.f;

    const int NT = DIMW/16;   // 32 kts of 16 kpairs

    // prologue: issue stages 0,1
    #pragma unroll
    for(int t=0;t<2;t++){
        const uint32_t st = smb + t*STAGEW*4;
        #pragma unroll
        for(int i=0;i<4;i++){
            int r = ar_ + i*32;
            cpa16(st + (r*AST+ac_)*4, Ab + (size_t)r*DIMW + t*16 + ac_);
            int rb = br_ + i*4;
            cpa16(st + (ABUFW + rb*BST + bc_)*4, Bb + (size_t)(t*16+rb)*N + bc_);
        }
        CPA_COMMIT();
    }

    for(int kt=0;kt<NT;kt++){
        if(kt<NT-1){ asm volatile("cp.async.wait_group 1;" ::: "memory"); }
        else       { asm volatile("cp.async.wait_group 0;" ::: "memory"); }
        __syncthreads();
        if(kt+2<NT){
            const uint32_t st = smb + ((kt+2)%3)*STAGEW*4;
            #pragma unroll
            for(int i=0;i<4;i++){
                int r = ar_ + i*32;
                cpa16(st + (r*AST+ac_)*4, Ab + (size_t)r*DIMW + (kt+2)*16 + ac_);
                int rb = br_ + i*4;
                cpa16(st + (ABUFW + rb*BST + bc_)*4, Bb + (size_t)((kt+2)*16+rb)*N + bc_);
            }
            CPA_COMMIT();
        }
        const unsigned* As = gsm + (kt%3)*STAGEW;
        const unsigned* Bs = As + ABUFW;
        #pragma unroll
        for(int ks=0;ks<2;ks++){
            const int k0=ks*8;
            unsigned af[4][4], bf[8][2];
            #pragma unroll
            for(int mi=0;mi<4;mi++){
                const int m0=mbase+mi*16;
                af[mi][0]=As[(m0+g  )*AST+k0+tg  ];
                af[mi][1]=As[(m0+g+8)*AST+k0+tg  ];
                af[mi][2]=As[(m0+g  )*AST+k0+tg+4];
                af[mi][3]=As[(m0+g+8)*AST+k0+tg+4];
            }
            #pragma unroll
            for(int ni=0;ni<8;ni++){
                const int n0=nbase+ni*8;
                bf[ni][0]=Bs[(k0+tg)*BST+n0+g];
                bf[ni][1]=Bs[(k0+tg+4)*BST+n0+g];
            }
            #pragma unroll
            for(int mi=0;mi<4;mi++)
                #pragma unroll
                for(int ni=0;ni<8;ni++)
                    mma16(acc[mi][ni],af[mi],bf[ni]);
        }
    }

    #pragma unroll
    for(int mi=0;mi<4;mi++){
        #pragma unroll
        for(int ni=0;ni<8;ni++){
            #pragma unroll
            for(int e2=0;e2<2;e2++){
                const int r = bm + mbase + mi*16 + g + (e2?8:0);
                const int c = bn + nbase + ni*8 + 2*tg;
                const float v0 = acc[mi][ni][e2*2+0] + bias[c];
                const float v1 = acc[mi][ni][e2*2+1] + bias[c+1];
                if(SCATTER){
                    const int b=r>>11, s=r&2047;
                    const int t=c>>10, h=(c>>6)&15, dp=(c&63)>>1;
                    g_qkv[((((size_t)t*BATCH+b)*NHEAD+h)*SEQ+s)*HDW+dp]=packh2(v0,v1);
                } else {
                    *(float2*)&out[(size_t)r*N+c]=make_float2(v0,v1);
                }
            }
        }
    }
}

// ---------------------------------------------------------------------------
// fp16 flash attention (R14 version, unchanged — proven at 459 µs run)
// ---------------------------------------------------------------------------
#define QKOFF ((size_t)BATCH*NHEAD*SEQ*HDW)
#define KVST 36
#define KVW (2*64*KVST)
#define QSTG (128*KVST)
#define FLASH_SMEM ((2*KVW + QSTG)*4)   /* 55296 B */

__global__ __launch_bounds__(128)
void flash_mma()
{
    extern __shared__ __align__(16) unsigned sm[];
    unsigned* Qst = sm + 2*KVW;
    const int tid=threadIdx.x, lane=tid&31, warp=tid>>5;
    const int g=lane>>2, tg=lane&3;
    const int qb=warp*32;
    const int b=blockIdx.y>>4, h=blockIdx.y&15;
    const int q0=blockIdx.x*128;
    const unsigned* Qg=g_qkv + ((size_t)(b*NHEAD+h))*SEQ*HDW;
    const unsigned* Kg=Qg + QKOFF;
    const unsigned* Vg=Kg + QKOFF;
    const uint32_t smb = smem_u32(sm);

    const int mat = lane>>3;
    const int ldmOff = (((mat&1)*8 + (lane&7))*KVST + (mat>>1)*4)*4;

    #pragma unroll
    for(int t=0;t<2;t++){
        const uint32_t kb = smb + t*KVW*4;
        #pragma unroll
        for(int i=0;i<4;i++){
            int idx=tid+(i<<7);
            int r=idx>>3, c4=(idx&7)<<2;
            cpa16(kb + (r*KVST+c4)*4,      Kg+(size_t)(t*64+r)*HDW+c4);
            cpa16(kb + ((64+r)*KVST+c4)*4, Vg+(size_t)(t*64+r)*HDW+c4);
        }
        CPA_COMMIT();
    }

    #pragma unroll
    for(int i=0;i<8;i++){
        int idx=tid+(i<<7);
        int r=idx>>3, c4=(idx&7)<<2;
        *(uint4*)&Qst[r*KVST+c4] = *(const uint4*)(Qg+(size_t)(q0+r)*HDW+c4);
    }
    __syncthreads();
    const float qs = 0.125f*1.44269504089f;
    unsigned qf[4][2][4];
    #pragma unroll
    for(int kg=0;kg<4;kg++){
        #pragma unroll
        for(int mi=0;mi<2;mi++){
            const int m0=qb+mi*16;
            #pragma unroll
            for(int s=0;s<4;s++){
                const int row = m0 + g + ((s&1)?8:0);
                const int dp  = kg*8 + tg + ((s>=2)?4:0);
                float2 v = uph2(Qst[row*KVST+dp]);
                qf[kg][mi][s] = packh2(v.x*qs, v.y*qs);
            }
        }
    }
    __syncthreads();

    float oc[2][8][4];
    #pragma unroll
    for(int mi=0;mi<2;mi++)
        #pragma unroll
        for(int i=0;i<8;i++)
            #pragma unroll
            for(int j=0;j<4;j++) oc[mi][i][j]=0.f;
    float mrow[4], lrow[4];
    #pragma unroll
    for(int i=0;i<4;i++){ mrow[i]=-1e30f; lrow[i]=0.f; }

    const int NKT = SEQ/64;
    for(int kt=0;kt<NKT;kt++){
        if(kt<NKT-1){ asm volatile("cp.async.wait_group 1;" ::: "memory"); }
        else        { asm volatile("cp.async.wait_group 0;" ::: "memory"); }
        __syncthreads();
        const unsigned* Kb = sm + (kt&1)*KVW;
        const uint32_t vbase = smb + ((kt&1)*KVW + 64*KVST)*4;

        float sc[2][8][4];
        #pragma unroll
        for(int mi=0;mi<2;mi++)
            #pragma unroll
            for(int i=0;i<8;i++)
                #pragma unroll
                for(int j=0;j<4;j++) sc[mi][i][j]=0.f;
        #pragma unroll
        for(int kg=0;kg<4;kg++){
            #pragma unroll
            for(int ni=0;ni<8;ni++){
                unsigned bf[2];
                bf[0]=Kb[(ni*8+g)*KVST + kg*8+tg];
                bf[1]=Kb[(ni*8+g)*KVST + kg*8+tg+4];
                mma16(sc[0][ni],qf[kg][0],bf);
                mma16(sc[1][ni],qf[kg][1],bf);
            }
        }

        float al[4];
        unsigned pk[2][8][2];
        #pragma unroll
        for(int mi=0;mi<2;mi++){
            float mx0=-1e30f, mx1=-1e30f;
            #pragma unroll
            for(int ni=0;ni<8;ni++){
                mx0=fmaxf(mx0,fmaxf(sc[mi][ni][0],sc[mi][ni][1]));
                mx1=fmaxf(mx1,fmaxf(sc[mi][ni][2],sc[mi][ni][3]));
            }
            mx0=fmaxf(mx0,__shfl_xor_sync(0xffffffffu,mx0,1));
            mx0=fmaxf(mx0,__shfl_xor_sync(0xffffffffu,mx0,2));
            mx1=fmaxf(mx1,__shfl_xor_sync(0xffffffffu,mx1,1));
            mx1=fmaxf(mx1,__shfl_xor_sync(0xffffffffu,mx1,2));
            const float nm0=fmaxf(mrow[mi*2],mx0), nm1=fmaxf(mrow[mi*2+1],mx1);
            al[mi*2]  =exp2f(mrow[mi*2]-nm0);
            al[mi*2+1]=exp2f(mrow[mi*2+1]-nm1);
            mrow[mi*2]=nm0; mrow[mi*2+1]=nm1;
            float s0=0.f, s1=0.f;
            #pragma unroll
            for(int ni=0;ni<8;ni++){
                float e0=exp2f(sc[mi][ni][0]-nm0);
                float e1=exp2f(sc[mi][ni][1]-nm0);
                float e2=exp2f(sc[mi][ni][2]-nm1);
                float e3=exp2f(sc[mi][ni][3]-nm1);
                s0+=e0+e1; s1+=e2+e3;
                pk[mi][ni][0]=packh2(e0,e1);
                pk[mi][ni][1]=packh2(e2,e3);
            }
            s0+=__shfl_xor_sync(0xffffffffu,s0,1); s0+=__shfl_xor_sync(0xffffffffu,s0,2);
            s1+=__shfl_xor_sync(0xffffffffu,s1,1); s1+=__shfl_xor_sync(0xffffffffu,s1,2);
            lrow[mi*2]  =lrow[mi*2]  *al[mi*2]  +s0;
            lrow[mi*2+1]=lrow[mi*2+1]*al[mi*2+1]+s1;
        }

        #pragma unroll
        for(int mi=0;mi<2;mi++)
            #pragma unroll
            for(int di=0;di<8;di++){
                oc[mi][di][0]*=al[mi*2];   oc[mi][di][1]*=al[mi*2];
                oc[mi][di][2]*=al[mi*2+1]; oc[mi][di][3]*=al[mi*2+1];
            }

        #pragma unroll
        for(int kg=0;kg<4;kg++){
            unsigned ap[2][4];
            #pragma unroll
            for(int mi=0;mi<2;mi++){
                ap[mi][0]=pk[mi][2*kg  ][0];
                ap[mi][1]=pk[mi][2*kg  ][1];
                ap[mi][2]=pk[mi][2*kg+1][0];
                ap[mi][3]=pk[mi][2*kg+1][1];
            }
            #pragma unroll
            for(int dd=0;dd<4;dd++){
                unsigned vr[4];
                ldmx4t(vr, vbase + ldmOff + (kg*16*KVST + dd*8)*4);
                mma16(oc[0][2*dd  ],ap[0],vr);
                mma16(oc[0][2*dd+1],ap[0],vr+2);
                mma16(oc[1][2*dd  ],ap[1],vr);
                mma16(oc[1][2*dd+1],ap[1],vr+2);
            }
        }
        __syncthreads();
        if(kt<NKT-2){
            const uint32_t kb = smb + (kt&1)*KVW*4;
            #pragma unroll
            for(int i=0;i<4;i++){
                int idx=tid+(i<<7);
                int r=idx>>3, c4=(idx&7)<<2;
                cpa16(kb + (r*KVST+c4)*4,      Kg+(size_t)((kt+2)*64+r)*HDW+c4);
                cpa16(kb + ((64+r)*KVST+c4)*4, Vg+(size_t)((kt+2)*64+r)*HDW+c4);
            }
            CPA_COMMIT();
        }
    }

    #pragma unroll
    for(int mi=0;mi<2;mi++){
        const float i0=1.f/lrow[mi*2], i1=1.f/lrow[mi*2+1];
        const int r0=q0+qb+mi*16+g, r1=r0+8;
        unsigned* O0=&g_attn[(size_t)(b*SEQ+r0)*DIMW + h*HDW];
        unsigned* O1=&g_attn[(size_t)(b*SEQ+r1)*DIMW + h*HDW];
        #pragma unroll
        for(int di=0;di<8;di++){
            O0[di*4+tg]=packh2(oc[mi][di][0]*i0, oc[mi][di][1]*i0);
            O1[di*4+tg]=packh2(oc[mi][di][2]*i1, oc[mi][di][3]*i1);
        }
    }
}

// ---------------------------------------------------------------------------
extern "C" void kernel_launch(void* const* d_in, const int* in_sizes, int n_in,
                              void* d_out, int out_size)
{
    const float* x     = (const float*)d_in[0];
    const float* Wqkv  = (const float*)d_in[1];
    const float* bqkv  = (const float*)d_in[2];
    const float* Wproj = (const float*)d_in[3];
    const float* bproj = (const float*)d_in[4];
    float* out = (float*)d_out;

    cudaFuncSetAttribute(flash_mma, cudaFuncAttributeMaxDynamicSharedMemorySize, FLASH_SMEM);
    cudaFuncSetAttribute(gemm_mma<NQKV,true>,  cudaFuncAttributeMaxDynamicSharedMemorySize, GEMM_SMEM);
    cudaFuncSetAttribute(gemm_mma<DIMC,false>, cudaFuncAttributeMaxDynamicSharedMemorySize, GEMM_SMEM);

    unsigned *xtf, *wqkv, *wprj;
    cudaGetSymbolAddress((void**)&xtf,  g_xtf);
    cudaGetSymbolAddress((void**)&wqkv, g_wqkv);
    cudaGetSymbolAddress((void**)&wprj, g_wprj);

    cvt_x<<<(MTOT*DIMC/4+255)/256, 256>>>((const float4*)x, (uint2*)xtf, MTOT*DIMC/4);
    cvt_w<<<(DIMW*NQKV+255)/256, 256>>>(Wqkv, wqkv, NQKV, DIMW*NQKV);
    cvt_w<<<(DIMW*DIMC+255)/256, 256>>>(Wproj, wprj, DIMC, DIMW*DIMC);

    dim3 g1(NQKV/128, MTOT/128);   // (24, 64)
    gemm_mma<NQKV, true><<<g1, 128, GEMM_SMEM>>>(xtf, wqkv, bqkv, nullptr);

    dim3 g2(SEQ/128, BATCH*NHEAD); // (16, 64)
    flash_mma<<<g2, 128, FLASH_SMEM>>>();

    dim3 g3(DIMC/128, MTOT/128);   // (8, 64)
    gemm_mma<DIMC, false><<<g3, 128, GEMM_SMEM>>>(nullptr, wprj, bproj, out);
}

// round 16
// speedup vs baseline: 1.0030x; 1.0030x over previous
#include <cuda_runtime.h>
#include <cuda_fp16.h>
#include <cstdint>

#define DIMC 1024
#define DIMW 512                 /* packed half2 words per row */
#define NHEAD 16
#define HDIM 64
#define HDW 32
#define BATCH 4
#define SEQ 2048
#define MTOT (BATCH*SEQ)
#define NQKV (3*DIMC)

__device__ unsigned g_xtf [(size_t)MTOT*DIMW];
__device__ unsigned g_wqkv[(size_t)DIMW*NQKV];   // [kpair][n]
__device__ unsigned g_wprj[(size_t)DIMW*DIMC];   // [kpair][n]
__device__ unsigned g_qkv [(size_t)3*BATCH*NHEAD*SEQ*HDW];  // [3][B][H][S][dpair]
__device__ unsigned g_attn[(size_t)MTOT*DIMW];

__device__ __forceinline__ unsigned packh2(float a, float b){
    __half2 h = __floats2half2_rn(a,b);
    return *(unsigned*)&h;
}
__device__ __forceinline__ float2 uph2(unsigned u){
    __half2 h = *(__half2*)&u;
    return __half22float2(h);
}
__device__ __forceinline__ void mma16(float* c, const unsigned* a, const unsigned* b){
    asm volatile(
      "mma.sync.aligned.m16n8k16.row.col.f32.f16.f16.f32 "
      "{%0,%1,%2,%3},{%4,%5,%6,%7},{%8,%9},{%0,%1,%2,%3};\n"
      : "+f"(c[0]),"+f"(c[1]),"+f"(c[2]),"+f"(c[3])
      : "r"(a[0]),"r"(a[1]),"r"(a[2]),"r"(a[3]),"r"(b[0]),"r"(b[1]));
}
__device__ __forceinline__ uint32_t smem_u32(const void* p){
    uint32_t a;
    asm("{ .reg .u64 t; cvta.to.shared.u64 t, %1; cvt.u32.u64 %0, t; }":"=r"(a):"l"(p));
    return a;
}
__device__ __forceinline__ void cpa16(uint32_t dst, const void* src){
    asm volatile("cp.async.cg.shared.global [%0], [%1], 16;" :: "r"(dst), "l"(src));
}
#define CPA_COMMIT() asm volatile("cp.async.commit_group;" ::: "memory")
__device__ __forceinline__ void ldmx4t(unsigned* r, uint32_t addr){
    asm volatile("ldmatrix.sync.aligned.m8n8.x4.trans.shared.b16 {%0,%1,%2,%3}, [%4];"
        : "=r"(r[0]),"=r"(r[1]),"=r"(r[2]),"=r"(r[3]) : "r"(addr));
}

// ---------------------------------------------------------------------------
// Conversions
// ---------------------------------------------------------------------------
__global__ __launch_bounds__(256)
void cvt_x(const float4* __restrict__ src, uint2* __restrict__ dst, int n4)
{
    int i = blockIdx.x*256 + threadIdx.x;
    if(i < n4){
        float4 v = src[i];
        dst[i] = make_uint2(packh2(v.x,v.y), packh2(v.z,v.w));
    }
}
__global__ __launch_bounds__(256)
void cvt_w(const float* __restrict__ src, unsigned* __restrict__ dst, int N, int tot)
{
    int i = blockIdx.x*256 + threadIdx.x;
    if(i < tot){
        int kp = i / N, n = i - kp*N;
        dst[i] = packh2(src[(size_t)(2*kp)*N+n], src[(size_t)(2*kp+1)*N+n]);
    }
}

// ---------------------------------------------------------------------------
// fp16 GEMM: 256 threads, warp tile 64x32 (8 warps: 2x4), 128x128 block,
// cp.async 3-stage ring. 2 CTAs/SM -> 16 warps/SM (4 per SMSP).
// A smem [m][kpair] stride 20; B smem [kpair][n] stride 136.
// ---------------------------------------------------------------------------
#define AST 20
#define ABUFW (128*AST)          /* 2560 words */
#define BST 136
#define BBUFW (16*BST)           /* 2176 words */
#define STAGEW (ABUFW+BBUFW)     /* 4736 words */
#define GEMM_SMEM (3*STAGEW*4)   /* 56832 B */

template<int N, bool SCATTER>
__global__ __launch_bounds__(256,2)
void gemm_mma(const unsigned* __restrict__ A, const unsigned* __restrict__ B,
              const float* __restrict__ bias, float* __restrict__ out)
{
    extern __shared__ __align__(16) unsigned gsm[];
    const int tid=threadIdx.x, lane=tid&31, warp=tid>>5;
    const int g=lane>>2, tg=lane&3;
    const int mbase=(warp&1)*64, nbase=(warp>>1)*32;
    const int bm=blockIdx.y*128, bn=blockIdx.x*128;
    const unsigned* Ab = (SCATTER ? A : (const unsigned*)g_attn) + (size_t)bm*DIMW;
    const unsigned* Bb = B + bn;
    const uint32_t smb = smem_u32(gsm);

    // per-thread fill coordinates (256 threads: 2 A + 2 B cp.async each)
    const int ar_ = tid>>2,  ac_ = (tid&3)<<2;     // A rows 0..63 (+64*i)
    const int br_ = tid>>5,  bc_ = (tid&31)<<2;    // B rows 0..7 (+8*i)

    float acc[4][4][4];
    #pragma unroll
    for(int i=0;i<4;i++)
      #pragma unroll
      for(int j=0;j<4;j++)
        #pragma unroll
        for(int k=0;k<4;k++) acc[i][j][k]=0.f;

    const int NT = DIMW/16;   // 32 kts of 16 kpairs

    #pragma unroll
    for(int t=0;t<2;t++){
        const uint32_t st = smb + t*STAGEW*4;
        #pragma unroll
        for(int i=0;i<2;i++){
            int r = ar_ + i*64;
            cpa16(st + (r*AST+ac_)*4, Ab + (size_t)r*DIMW + t*16 + ac_);
            int rb = br_ + i*8;
            cpa16(st + (ABUFW + rb*BST + bc_)*4, Bb + (size_t)(t*16+rb)*N + bc_);
        }
        CPA_COMMIT();
    }

    for(int kt=0;kt<NT;kt++){
        if(kt<NT-1){ asm volatile("cp.async.wait_group 1;" ::: "memory"); }
        else       { asm volatile("cp.async.wait_group 0;" ::: "memory"); }
        __syncthreads();
        if(kt+2<NT){
            const uint32_t st = smb + ((kt+2)%3)*STAGEW*4;
            #pragma unroll
            for(int i=0;i<2;i++){
                int r = ar_ + i*64;
                cpa16(st + (r*AST+ac_)*4, Ab + (size_t)r*DIMW + (kt+2)*16 + ac_);
                int rb = br_ + i*8;
                cpa16(st + (ABUFW + rb*BST + bc_)*4, Bb + (size_t)((kt+2)*16+rb)*N + bc_);
            }
            CPA_COMMIT();
        }
        const unsigned* As = gsm + (kt%3)*STAGEW;
        const unsigned* Bs = As + ABUFW;
        #pragma unroll
        for(int ks=0;ks<2;ks++){
            const int k0=ks*8;
            unsigned af[4][4], bf[4][2];
            #pragma unroll
            for(int mi=0;mi<4;mi++){
                const int m0=mbase+mi*16;
                af[mi][0]=As[(m0+g  )*AST+k0+tg  ];
                af[mi][1]=As[(m0+g+8)*AST+k0+tg  ];
                af[mi][2]=As[(m0+g  )*AST+k0+tg+4];
                af[mi][3]=As[(m0+g+8)*AST+k0+tg+4];
            }
            #pragma unroll
            for(int ni=0;ni<4;ni++){
                const int n0=nbase+ni*8;
                bf[ni][0]=Bs[(k0+tg)*BST+n0+g];
                bf[ni][1]=Bs[(k0+tg+4)*BST+n0+g];
            }
            #pragma unroll
            for(int mi=0;mi<4;mi++)
                #pragma unroll
                for(int ni=0;ni<4;ni++)
                    mma16(acc[mi][ni],af[mi],bf[ni]);
        }
    }

    #pragma unroll
    for(int mi=0;mi<4;mi++){
        #pragma unroll
        for(int ni=0;ni<4;ni++){
            #pragma unroll
            for(int e2=0;e2<2;e2++){
                const int r = bm + mbase + mi*16 + g + (e2?8:0);
                const int c = bn + nbase + ni*8 + 2*tg;
                const float v0 = acc[mi][ni][e2*2+0] + bias[c];
                const float v1 = acc[mi][ni][e2*2+1] + bias[c+1];
                if(SCATTER){
                    const int b=r>>11, s=r&2047;
                    const int t=c>>10, h=(c>>6)&15, dp=(c&63)>>1;
                    g_qkv[((((size_t)t*BATCH+b)*NHEAD+h)*SEQ+s)*HDW+dp]=packh2(v0,v1);
                } else {
                    *(float2*)&out[(size_t)r*N+c]=make_float2(v0,v1);
                }
            }
        }
    }
}

// ---------------------------------------------------------------------------
// fp16 flash attention (R14 version, unchanged)
// ---------------------------------------------------------------------------
#define QKOFF ((size_t)BATCH*NHEAD*SEQ*HDW)
#define KVST 36
#define KVW (2*64*KVST)
#define QSTG (128*KVST)
#define FLASH_SMEM ((2*KVW + QSTG)*4)   /* 55296 B */

__global__ __launch_bounds__(128)
void flash_mma()
{
    extern __shared__ __align__(16) unsigned sm[];
    unsigned* Qst = sm + 2*KVW;
    const int tid=threadIdx.x, lane=tid&31, warp=tid>>5;
    const int g=lane>>2, tg=lane&3;
    const int qb=warp*32;
    const int b=blockIdx.y>>4, h=blockIdx.y&15;
    const int q0=blockIdx.x*128;
    const unsigned* Qg=g_qkv + ((size_t)(b*NHEAD+h))*SEQ*HDW;
    const unsigned* Kg=Qg + QKOFF;
    const unsigned* Vg=Kg + QKOFF;
    const uint32_t smb = smem_u32(sm);

    const int mat = lane>>3;
    const int ldmOff = (((mat&1)*8 + (lane&7))*KVST + (mat>>1)*4)*4;

    #pragma unroll
    for(int t=0;t<2;t++){
        const uint32_t kb = smb + t*KVW*4;
        #pragma unroll
        for(int i=0;i<4;i++){
            int idx=tid+(i<<7);
            int r=idx>>3, c4=(idx&7)<<2;
            cpa16(kb + (r*KVST+c4)*4,      Kg+(size_t)(t*64+r)*HDW+c4);
            cpa16(kb + ((64+r)*KVST+c4)*4, Vg+(size_t)(t*64+r)*HDW+c4);
        }
        CPA_COMMIT();
    }

    #pragma unroll
    for(int i=0;i<8;i++){
        int idx=tid+(i<<7);
        int r=idx>>3, c4=(idx&7)<<2;
        *(uint4*)&Qst[r*KVST+c4] = *(const uint4*)(Qg+(size_t)(q0+r)*HDW+c4);
    }
    __syncthreads();
    const float qs = 0.125f*1.44269504089f;
    unsigned qf[4][2][4];
    #pragma unroll
    for(int kg=0;kg<4;kg++){
        #pragma unroll
        for(int mi=0;mi<2;mi++){
            const int m0=qb+mi*16;
            #pragma unroll
            for(int s=0;s<4;s++){
                const int row = m0 + g + ((s&1)?8:0);
                const int dp  = kg*8 + tg + ((s>=2)?4:0);
                float2 v = uph2(Qst[row*KVST+dp]);
                qf[kg][mi][s] = packh2(v.x*qs, v.y*qs);
            }
        }
    }
    __syncthreads();

    float oc[2][8][4];
    #pragma unroll
    for(int mi=0;mi<2;mi++)
        #pragma unroll
        for(int i=0;i<8;i++)
            #pragma unroll
            for(int j=0;j<4;j++) oc[mi][i][j]=0.f;
    float mrow[4], lrow[4];
    #pragma unroll
    for(int i=0;i<4;i++){ mrow[i]=-1e30f; lrow[i]=0.f; }

    const int NKT = SEQ/64;
    for(int kt=0;kt<NKT;kt++){
        if(kt<NKT-1){ asm volatile("cp.async.wait_group 1;" ::: "memory"); }
        else        { asm volatile("cp.async.wait_group 0;" ::: "memory"); }
        __syncthreads();
        const unsigned* Kb = sm + (kt&1)*KVW;
        const uint32_t vbase = smb + ((kt&1)*KVW + 64*KVST)*4;

        float sc[2][8][4];
        #pragma unroll
        for(int mi=0;mi<2;mi++)
            #pragma unroll
            for(int i=0;i<8;i++)
                #pragma unroll
                for(int j=0;j<4;j++) sc[mi][i][j]=0.f;
        #pragma unroll
        for(int kg=0;kg<4;kg++){
            #pragma unroll
            for(int ni=0;ni<8;ni++){
                unsigned bf[2];
                bf[0]=Kb[(ni*8+g)*KVST + kg*8+tg];
                bf[1]=Kb[(ni*8+g)*KVST + kg*8+tg+4];
                mma16(sc[0][ni],qf[kg][0],bf);
                mma16(sc[1][ni],qf[kg][1],bf);
            }
        }

        float al[4];
        unsigned pk[2][8][2];
        #pragma unroll
        for(int mi=0;mi<2;mi++){
            float mx0=-1e30f, mx1=-1e30f;
            #pragma unroll
            for(int ni=0;ni<8;ni++){
                mx0=fmaxf(mx0,fmaxf(sc[mi][ni][0],sc[mi][ni][1]));
                mx1=fmaxf(mx1,fmaxf(sc[mi][ni][2],sc[mi][ni][3]));
            }
            mx0=fmaxf(mx0,__shfl_xor_sync(0xffffffffu,mx0,1));
            mx0=fmaxf(mx0,__shfl_xor_sync(0xffffffffu,mx0,2));
            mx1=fmaxf(mx1,__shfl_xor_sync(0xffffffffu,mx1,1));
            mx1=fmaxf(mx1,__shfl_xor_sync(0xffffffffu,mx1,2));
            const float nm0=fmaxf(mrow[mi*2],mx0), nm1=fmaxf(mrow[mi*2+1],mx1);
            al[mi*2]  =exp2f(mrow[mi*2]-nm0);
            al[mi*2+1]=exp2f(mrow[mi*2+1]-nm1);
            mrow[mi*2]=nm0; mrow[mi*2+1]=nm1;
            float s0=0.f, s1=0.f;
            #pragma unroll
            for(int ni=0;ni<8;ni++){
                float e0=exp2f(sc[mi][ni][0]-nm0);
                float e1=exp2f(sc[mi][ni][1]-nm0);
                float e2=exp2f(sc[mi][ni][2]-nm1);
                float e3=exp2f(sc[mi][ni][3]-nm1);
                s0+=e0+e1; s1+=e2+e3;
                pk[mi][ni][0]=packh2(e0,e1);
                pk[mi][ni][1]=packh2(e2,e3);
            }
            s0+=__shfl_xor_sync(0xffffffffu,s0,1); s0+=__shfl_xor_sync(0xffffffffu,s0,2);
            s1+=__shfl_xor_sync(0xffffffffu,s1,1); s1+=__shfl_xor_sync(0xffffffffu,s1,2);
            lrow[mi*2]  =lrow[mi*2]  *al[mi*2]  +s0;
            lrow[mi*2+1]=lrow[mi*2+1]*al[mi*2+1]+s1;
        }

        #pragma unroll
        for(int mi=0;mi<2;mi++)
            #pragma unroll
            for(int di=0;di<8;di++){
                oc[mi][di][0]*=al[mi*2];   oc[mi][di][1]*=al[mi*2];
                oc[mi][di][2]*=al[mi*2+1]; oc[mi][di][3]*=al[mi*2+1];
            }

        #pragma unroll
        for(int kg=0;kg<4;kg++){
            unsigned ap[2][4];
            #pragma unroll
            for(int mi=0;mi<2;mi++){
                ap[mi][0]=pk[mi][2*kg  ][0];
                ap[mi][1]=pk[mi][2*kg  ][1];
                ap[mi][2]=pk[mi][2*kg+1][0];
                ap[mi][3]=pk[mi][2*kg+1][1];
            }
            #pragma unroll
            for(int dd=0;dd<4;dd++){
                unsigned vr[4];
                ldmx4t(vr, vbase + ldmOff + (kg*16*KVST + dd*8)*4);
                mma16(oc[0][2*dd  ],ap[0],vr);
                mma16(oc[0][2*dd+1],ap[0],vr+2);
                mma16(oc[1][2*dd  ],ap[1],vr);
                mma16(oc[1][2*dd+1],ap[1],vr+2);
            }
        }
        __syncthreads();
        if(kt<NKT-2){
            const uint32_t kb = smb + (kt&1)*KVW*4;
            #pragma unroll
            for(int i=0;i<4;i++){
                int idx=tid+(i<<7);
                int r=idx>>3, c4=(idx&7)<<2;
                cpa16(kb + (r*KVST+c4)*4,      Kg+(size_t)((kt+2)*64+r)*HDW+c4);
                cpa16(kb + ((64+r)*KVST+c4)*4, Vg+(size_t)((kt+2)*64+r)*HDW+c4);
            }
            CPA_COMMIT();
        }
    }

    #pragma unroll
    for(int mi=0;mi<2;mi++){
        const float i0=1.f/lrow[mi*2], i1=1.f/lrow[mi*2+1];
        const int r0=q0+qb+mi*16+g, r1=r0+8;
        unsigned* O0=&g_attn[(size_t)(b*SEQ+r0)*DIMW + h*HDW];
        unsigned* O1=&g_attn[(size_t)(b*SEQ+r1)*DIMW + h*HDW];
        #pragma unroll
        for(int di=0;di<8;di++){
            O0[di*4+tg]=packh2(oc[mi][di][0]*i0, oc[mi][di][1]*i0);
            O1[di*4+tg]=packh2(oc[mi][di][2]*i1, oc[mi][di][3]*i1);
        }
    }
}

// ---------------------------------------------------------------------------
extern "C" void kernel_launch(void* const* d_in, const int* in_sizes, int n_in,
                              void* d_out, int out_size)
{
    const float* x     = (const float*)d_in[0];
    const float* Wqkv  = (const float*)d_in[1];
    const float* bqkv  = (const float*)d_in[2];
    const float* Wproj = (const float*)d_in[3];
    const float* bproj = (const float*)d_in[4];
    float* out = (float*)d_out;

    cudaFuncSetAttribute(flash_mma, cudaFuncAttributeMaxDynamicSharedMemorySize, FLASH_SMEM);
    cudaFuncSetAttribute(gemm_mma<NQKV,true>,  cudaFuncAttributeMaxDynamicSharedMemorySize, GEMM_SMEM);
    cudaFuncSetAttribute(gemm_mma<DIMC,false>, cudaFuncAttributeMaxDynamicSharedMemorySize, GEMM_SMEM);

    unsigned *xtf, *wqkv, *wprj;
    cudaGetSymbolAddress((void**)&xtf,  g_xtf);
    cudaGetSymbolAddress((void**)&wqkv, g_wqkv);
    cudaGetSymbolAddress((void**)&wprj, g_wprj);

    cvt_x<<<(MTOT*DIMC/4+255)/256, 256>>>((const float4*)x, (uint2*)xtf, MTOT*DIMC/4);
    cvt_w<<<(DIMW*NQKV+255)/256, 256>>>(Wqkv, wqkv, NQKV, DIMW*NQKV);
    cvt_w<<<(DIMW*DIMC+255)/256, 256>>>(Wproj, wprj, DIMC, DIMW*DIMC);

    dim3 g1(NQKV/128, MTOT/128);   // (24, 64)
    gemm_mma<NQKV, true><<<g1, 256, GEMM_SMEM>>>(xtf, wqkv, bqkv, nullptr);

    dim3 g2(SEQ/128, BATCH*NHEAD); // (16, 64)
    flash_mma<<<g2, 128, FLASH_SMEM>>>();

    dim3 g3(DIMC/128, MTOT/128);   // (8, 64)
    gemm_mma<DIMC, false><<<g3, 256, GEMM_SMEM>>>(nullptr, wprj, bproj, out);
}